// round 1
// baseline (speedup 1.0000x reference)
#include <cuda_runtime.h>
#include <math.h>

#define BATCH    4
#define HEADS    16
#define SEQ      2048
#define DIM      64
#define BM       64
#define BN       64
#define NTHREADS 256
#define QSTRIDE  65   // pad to break stride-64 bank conflicts on per-row reads
#define KSTRIDE  65

// Flash-attention fp32. Block computes BM=64 query rows for one (b,h),
// streaming KV in BN=64 tiles with online softmax.
// Threads laid out 16x16 (tx fast); each thread owns a 4x4 S/P fragment
// (rows ty*4.., key-cols tx*4..) and a 4x4 O fragment (rows ty*4.., dims tx*4..).
__global__ __launch_bounds__(NTHREADS, 2)
void attn_kernel(const float* __restrict__ q, const float* __restrict__ k,
                 const float* __restrict__ v, float* __restrict__ out) {
    extern __shared__ float sm[];
    float* Qs = sm;                    // BM x QSTRIDE
    float* Ks = Qs + BM * QSTRIDE;     // BN x KSTRIDE
    float* Vs = Ks + BN * KSTRIDE;     // BN x DIM   (stride 64: float4-friendly)
    float* Ps = Vs + BN * DIM;         // BM x DIM

    const int tid = threadIdx.x;
    const int tx = tid & 15;
    const int ty = tid >> 4;

    const int qblk = blockIdx.x;
    const int h    = blockIdx.y;
    const int b    = blockIdx.z;

    const float* qg = q + ((size_t)((b * HEADS + h) * SEQ + qblk * BM)) * DIM;
    const float* kg = k + (size_t)b * SEQ * DIM;
    const float* vg = v + (size_t)b * SEQ * DIM;
    float*       og = out + ((size_t)((b * HEADS + h) * SEQ + qblk * BM)) * DIM;

    const float scale = 0.125f;  // 1/sqrt(64), folded into Q at load

    // ---- load Q tile (prescaled), float4 global reads, scalar padded stores ----
    #pragma unroll
    for (int i = tid; i < BM * DIM / 4; i += NTHREADS) {
        float4 t = ((const float4*)qg)[i];
        int r = i >> 4;
        int c = (i & 15) << 2;
        float* dst = Qs + r * QSTRIDE + c;
        dst[0] = t.x * scale; dst[1] = t.y * scale;
        dst[2] = t.z * scale; dst[3] = t.w * scale;
    }

    float m[4], l[4], acc[4][4];
    #pragma unroll
    for (int i = 0; i < 4; i++) {
        m[i] = -INFINITY;
        l[i] = 0.f;
        #pragma unroll
        for (int j = 0; j < 4; j++) acc[i][j] = 0.f;
    }

    const int r0 = ty * 4;
    const int c0 = tx * 4;

    for (int kt = 0; kt < SEQ / BN; kt++) {
        __syncthreads();  // previous tile's PV reads of Vs/Ps are done

        // ---- load K (padded stride) and V (stride 64) tiles ----
        const float4* kgt = (const float4*)(kg + (size_t)kt * BN * DIM);
        const float4* vgt = (const float4*)(vg + (size_t)kt * BN * DIM);
        #pragma unroll
        for (int i = tid; i < BN * DIM / 4; i += NTHREADS) {
            float4 t = kgt[i];
            int r = i >> 4;
            int c = (i & 15) << 2;
            float* dst = Ks + r * KSTRIDE + c;
            dst[0] = t.x; dst[1] = t.y; dst[2] = t.z; dst[3] = t.w;
            ((float4*)Vs)[i] = vgt[i];
        }
        __syncthreads();

        // ---- S = Qs @ Ks^T (outer-product over d; Q reads broadcast, K reads 2-way max) ----
        float s[4][4];
        #pragma unroll
        for (int i = 0; i < 4; i++)
            #pragma unroll
            for (int j = 0; j < 4; j++) s[i][j] = 0.f;

        #pragma unroll 16
        for (int d = 0; d < DIM; d++) {
            float qf[4], kf[4];
            #pragma unroll
            for (int i = 0; i < 4; i++) qf[i] = Qs[(r0 + i) * QSTRIDE + d];
            #pragma unroll
            for (int j = 0; j < 4; j++) kf[j] = Ks[(c0 + j) * KSTRIDE + d];
            #pragma unroll
            for (int i = 0; i < 4; i++)
                #pragma unroll
                for (int j = 0; j < 4; j++)
                    s[i][j] = fmaf(qf[i], kf[j], s[i][j]);
        }

        // ---- online softmax: row stats reduced across the 16-lane tx group ----
        #pragma unroll
        for (int i = 0; i < 4; i++) {
            float rmax = fmaxf(fmaxf(s[i][0], s[i][1]), fmaxf(s[i][2], s[i][3]));
            #pragma unroll
            for (int off = 8; off >= 1; off >>= 1)
                rmax = fmaxf(rmax, __shfl_xor_sync(0xffffffffu, rmax, off));
            float mnew = fmaxf(m[i], rmax);
            float corr = __expf(m[i] - mnew);   // first tile: exp(-inf)=0
            float rsum = 0.f;
            #pragma unroll
            for (int j = 0; j < 4; j++) {
                s[i][j] = __expf(s[i][j] - mnew);
                rsum += s[i][j];
            }
            #pragma unroll
            for (int off = 8; off >= 1; off >>= 1)
                rsum += __shfl_xor_sync(0xffffffffu, rsum, off);
            l[i] = l[i] * corr + rsum;
            m[i] = mnew;
            #pragma unroll
            for (int j = 0; j < 4; j++) acc[i][j] *= corr;
        }

        // ---- stage P to smem (float4, 2-way max) ----
        #pragma unroll
        for (int i = 0; i < 4; i++) {
            float4 pv = make_float4(s[i][0], s[i][1], s[i][2], s[i][3]);
            *((float4*)&Ps[(r0 + i) * DIM + c0]) = pv;
        }
        __syncthreads();

        // ---- O += P @ V (P reads broadcast, V reads float4 conflict-free) ----
        #pragma unroll 8
        for (int j0 = 0; j0 < BN; j0++) {
            float4 v4 = *((const float4*)&Vs[j0 * DIM + c0]);
            #pragma unroll
            for (int i = 0; i < 4; i++) {
                float pf = Ps[(r0 + i) * DIM + j0];
                acc[i][0] = fmaf(pf, v4.x, acc[i][0]);
                acc[i][1] = fmaf(pf, v4.y, acc[i][1]);
                acc[i][2] = fmaf(pf, v4.z, acc[i][2]);
                acc[i][3] = fmaf(pf, v4.w, acc[i][3]);
            }
        }
    }

    // ---- epilogue: normalize and store (coalesced float4) ----
    #pragma unroll
    for (int i = 0; i < 4; i++) {
        float inv = 1.0f / l[i];
        float4 o = make_float4(acc[i][0] * inv, acc[i][1] * inv,
                               acc[i][2] * inv, acc[i][3] * inv);
        ((float4*)(og + (size_t)(r0 + i) * DIM))[tx] = o;
    }
}

extern "C" void kernel_launch(void* const* d_in, const int* in_sizes, int n_in,
                              void* d_out, int out_size) {
    const float* q = (const float*)d_in[0];
    const float* k = (const float*)d_in[1];
    const float* v = (const float*)d_in[2];
    float* o = (float*)d_out;

    const int smem_bytes =
        (BM * QSTRIDE + BN * KSTRIDE + BN * DIM + BM * DIM) * (int)sizeof(float);  // 66048

    cudaFuncSetAttribute(attn_kernel,
                         cudaFuncAttributeMaxDynamicSharedMemorySize, smem_bytes);

    dim3 grid(SEQ / BM, HEADS, BATCH);  // (32, 16, 4) = 2048 blocks
    attn_kernel<<<grid, NTHREADS, smem_bytes>>>(q, k, v, o);
}

// round 2
// speedup vs baseline: 1.0316x; 1.0316x over previous
#include <cuda_runtime.h>
#include <math.h>

#define BATCH    4
#define HEADS    16
#define SEQ      2048
#define DIM      64
#define BM       64
#define BN       64
#define NTHREADS 256

// float4-granular strides (in float4 units)
#define QS4  17   // Q tile: 64 rows x 16 f4, stride 17 -> bank16 = (r + c4) & 7
#define KS4  17   // K tile: same layout
#define VS4  16   // V tile: 64 rows x 16 f4, natural stride
#define PS4  17   // P tile: rows 16B-aligned, broadcast reads

// Flash-attention fp32, fully vectorized smem traffic.
// Thread grid 16x16 (tx fast). Fragments per thread:
//   S[i][j]: rows 4*ty+i, key-cols tx+16*j   (strided cols -> conflict-free K.f4)
//   O[i][c]: rows 4*ty+i, dim-cols 4*tx+c    (contiguous cols -> conflict-free V.f4)
// P goes through smem, remapping strided S-cols to contiguous j.
__global__ __launch_bounds__(NTHREADS, 2)
void attn_kernel(const float* __restrict__ q, const float* __restrict__ k,
                 const float* __restrict__ v, float* __restrict__ out) {
    extern __shared__ float4 sm4[];
    float4* Qs = sm4;                  // BM * QS4
    float4* Ks = Qs + BM * QS4;        // BN * KS4
    float4* Vs = Ks + BN * KS4;        // BN * VS4
    float4* Ps = Vs + BN * VS4;        // BM * PS4
    float*  Pf = (float*)Ps;

    const int tid = threadIdx.x;
    const int tx = tid & 15;
    const int ty = tid >> 4;

    const int qblk = blockIdx.x;
    const int h    = blockIdx.y;
    const int b    = blockIdx.z;

    const float* qg = q + ((size_t)((b * HEADS + h) * SEQ + qblk * BM)) * DIM;
    const float* kg = k + (size_t)b * SEQ * DIM;
    const float* vg = v + (size_t)b * SEQ * DIM;
    float*       og = out + ((size_t)((b * HEADS + h) * SEQ + qblk * BM)) * DIM;

    const float scale = 0.125f;  // 1/sqrt(64), folded into Q

    // ---- stage Q tile (prescaled), float4 in, float4 out (conflict-free) ----
    #pragma unroll
    for (int i = tid; i < BM * DIM / 4; i += NTHREADS) {
        float4 t = ((const float4*)qg)[i];
        t.x *= scale; t.y *= scale; t.z *= scale; t.w *= scale;
        Qs[(i >> 4) * QS4 + (i & 15)] = t;
    }

    float m[4], l[4], acc[4][4];
    #pragma unroll
    for (int i = 0; i < 4; i++) {
        m[i] = -INFINITY;
        l[i] = 0.f;
        #pragma unroll
        for (int j = 0; j < 4; j++) acc[i][j] = 0.f;
    }

    const int r0 = ty * 4;   // fragment rows r0..r0+3
    const int c0 = tx * 4;   // O fragment dim-cols c0..c0+3

    for (int kt = 0; kt < SEQ / BN; kt++) {
        __syncthreads();  // prior tile's PV reads of Vs done

        // ---- stage K (stride 17 f4) and V (stride 16 f4) ----
        const float4* kgt = (const float4*)(kg + (size_t)kt * BN * DIM);
        const float4* vgt = (const float4*)(vg + (size_t)kt * BN * DIM);
        #pragma unroll
        for (int i = tid; i < BN * DIM / 4; i += NTHREADS) {
            Ks[(i >> 4) * KS4 + (i & 15)] = kgt[i];
            Vs[i] = vgt[i];
        }
        __syncthreads();

        // ---- S = Q @ K^T, d chunked by 4, all loads LDS.128 ----
        float s[4][4];
        #pragma unroll
        for (int i = 0; i < 4; i++)
            #pragma unroll
            for (int j = 0; j < 4; j++) s[i][j] = 0.f;

        #pragma unroll 4
        for (int c4 = 0; c4 < DIM / 4; c4++) {
            float4 qf[4], kf[4];
            #pragma unroll
            for (int i = 0; i < 4; i++) qf[i] = Qs[(r0 + i) * QS4 + c4];
            #pragma unroll
            for (int j = 0; j < 4; j++) kf[j] = Ks[(tx + 16 * j) * KS4 + c4];
            #pragma unroll
            for (int i = 0; i < 4; i++)
                #pragma unroll
                for (int j = 0; j < 4; j++) {
                    s[i][j] = fmaf(qf[i].x, kf[j].x, s[i][j]);
                    s[i][j] = fmaf(qf[i].y, kf[j].y, s[i][j]);
                    s[i][j] = fmaf(qf[i].z, kf[j].z, s[i][j]);
                    s[i][j] = fmaf(qf[i].w, kf[j].w, s[i][j]);
                }
        }

        // ---- online softmax: row stats across the 16-lane tx group ----
        #pragma unroll
        for (int i = 0; i < 4; i++) {
            float rmax = fmaxf(fmaxf(s[i][0], s[i][1]), fmaxf(s[i][2], s[i][3]));
            #pragma unroll
            for (int off = 8; off >= 1; off >>= 1)
                rmax = fmaxf(rmax, __shfl_xor_sync(0xffffffffu, rmax, off));
            float mnew = fmaxf(m[i], rmax);
            float corr = __expf(m[i] - mnew);   // first tile: exp(-inf)=0
            float rsum = 0.f;
            #pragma unroll
            for (int j = 0; j < 4; j++) {
                s[i][j] = __expf(s[i][j] - mnew);
                rsum += s[i][j];
            }
            #pragma unroll
            for (int off = 8; off >= 1; off >>= 1)
                rsum += __shfl_xor_sync(0xffffffffu, rsum, off);
            l[i] = l[i] * corr + rsum;
            m[i] = mnew;
            #pragma unroll
            for (int j = 0; j < 4; j++) acc[i][j] *= corr;
        }

        // ---- store P: scalar, strided cols -> contiguous rows (conflict-free) ----
        #pragma unroll
        for (int i = 0; i < 4; i++)
            #pragma unroll
            for (int j = 0; j < 4; j++)
                Pf[(r0 + i) * (4 * PS4) + tx + 16 * j] = s[i][j];
        __syncthreads();

        // ---- O += P @ V, j chunked by 4, all loads LDS.128 ----
        #pragma unroll 4
        for (int jc = 0; jc < BN / 4; jc++) {
            float4 vf[4], pf[4];
            #pragma unroll
            for (int jj = 0; jj < 4; jj++) vf[jj] = Vs[(4 * jc + jj) * VS4 + tx];
            #pragma unroll
            for (int i = 0; i < 4; i++) pf[i] = Ps[(r0 + i) * PS4 + jc];
            #pragma unroll
            for (int i = 0; i < 4; i++) {
                acc[i][0] = fmaf(pf[i].x, vf[0].x, acc[i][0]);
                acc[i][1] = fmaf(pf[i].x, vf[0].y, acc[i][1]);
                acc[i][2] = fmaf(pf[i].x, vf[0].z, acc[i][2]);
                acc[i][3] = fmaf(pf[i].x, vf[0].w, acc[i][3]);
                acc[i][0] = fmaf(pf[i].y, vf[1].x, acc[i][0]);
                acc[i][1] = fmaf(pf[i].y, vf[1].y, acc[i][1]);
                acc[i][2] = fmaf(pf[i].y, vf[1].z, acc[i][2]);
                acc[i][3] = fmaf(pf[i].y, vf[1].w, acc[i][3]);
                acc[i][0] = fmaf(pf[i].z, vf[2].x, acc[i][0]);
                acc[i][1] = fmaf(pf[i].z, vf[2].y, acc[i][1]);
                acc[i][2] = fmaf(pf[i].z, vf[2].z, acc[i][2]);
                acc[i][3] = fmaf(pf[i].z, vf[2].w, acc[i][3]);
                acc[i][0] = fmaf(pf[i].w, vf[3].x, acc[i][0]);
                acc[i][1] = fmaf(pf[i].w, vf[3].y, acc[i][1]);
                acc[i][2] = fmaf(pf[i].w, vf[3].z, acc[i][2]);
                acc[i][3] = fmaf(pf[i].w, vf[3].w, acc[i][3]);
            }
        }
    }

    // ---- epilogue: normalize and store (coalesced float4) ----
    #pragma unroll
    for (int i = 0; i < 4; i++) {
        float inv = 1.0f / l[i];
        float4 o = make_float4(acc[i][0] * inv, acc[i][1] * inv,
                               acc[i][2] * inv, acc[i][3] * inv);
        ((float4*)(og + (size_t)(r0 + i) * DIM))[tx] = o;
    }
}

extern "C" void kernel_launch(void* const* d_in, const int* in_sizes, int n_in,
                              void* d_out, int out_size) {
    const float* q = (const float*)d_in[0];
    const float* k = (const float*)d_in[1];
    const float* v = (const float*)d_in[2];
    float* o = (float*)d_out;

    const int smem_bytes =
        (BM * QS4 + BN * KS4 + BN * VS4 + BM * PS4) * (int)sizeof(float4);  // 68608

    cudaFuncSetAttribute(attn_kernel,
                         cudaFuncAttributeMaxDynamicSharedMemorySize, smem_bytes);

    dim3 grid(SEQ / BM, HEADS, BATCH);  // (32, 16, 4) = 2048 blocks
    attn_kernel<<<grid, NTHREADS, smem_bytes>>>(q, k, v, o);
}

// round 3
// speedup vs baseline: 3.1039x; 3.0087x over previous
#include <cuda_runtime.h>
#include <math.h>
#include <stdint.h>

#define BATCH    4
#define HEADS    16
#define SEQ      2048
#define DIM      64
#define BM       64
#define BN       64
#define NTHREADS 128   // 4 warps, 16 query rows each

// smem strides in floats (chosen for conflict-free scalar fragment loads)
#define QST 68
#define KST 68
#define VST 72
#define PST 68

__device__ __forceinline__ float f2tf32(float x) {
    uint32_t r;
    asm("cvt.rna.tf32.f32 %0, %1;" : "=r"(r) : "f"(x));
    return __uint_as_float(r);
}

__device__ __forceinline__ void mma_tf32(float c[4], const uint32_t a[4], const uint32_t b[2]) {
    asm volatile(
        "mma.sync.aligned.m16n8k8.row.col.f32.tf32.tf32.f32 "
        "{%0,%1,%2,%3}, {%4,%5,%6,%7}, {%8,%9}, {%0,%1,%2,%3};\n"
        : "+f"(c[0]), "+f"(c[1]), "+f"(c[2]), "+f"(c[3])
        : "r"(a[0]), "r"(a[1]), "r"(a[2]), "r"(a[3]), "r"(b[0]), "r"(b[1]));
}

// Flash-attention, tf32 tensor cores, fp32 accumulate.
// Warp w owns query rows [16w, 16w+16). Per-thread mma fragment layout (m16n8k8):
//   A: a0=(g,t) a1=(g+8,t) a2=(g,t+4) a3=(g+8,t+4)   g=lane>>2, t=lane&3
//   B: b0=(k=t,n=g) b1=(k=t+4,n=g)
//   C: c0=(g,2t) c1=(g,2t+1) c2=(g+8,2t) c3=(g+8,2t+1)
__global__ __launch_bounds__(NTHREADS, 3)
void attn_kernel(const float* __restrict__ q, const float* __restrict__ k,
                 const float* __restrict__ v, float* __restrict__ out) {
    extern __shared__ float sm[];
    float* Qs = sm;                  // BM x QST
    float* Ks = Qs + BM * QST;       // BN x KST
    float* Vs = Ks + BN * KST;       // BN x VST
    float* Ps = Vs + BN * VST;       // BM x PST

    const int tid  = threadIdx.x;
    const int wid  = tid >> 5;
    const int lane = tid & 31;
    const int g = lane >> 2;   // groupID (row within m16 half)
    const int t = lane & 3;    // thread-in-group

    const int qblk = blockIdx.x;
    const int h    = blockIdx.y;
    const int b    = blockIdx.z;

    const float* qg = q + ((size_t)((b * HEADS + h) * SEQ + qblk * BM)) * DIM;
    const float* kg = k + (size_t)b * SEQ * DIM;
    const float* vg = v + (size_t)b * SEQ * DIM;
    float*       og = out + ((size_t)((b * HEADS + h) * SEQ + qblk * BM)) * DIM;

    const float scale = 0.125f;  // 1/sqrt(64), folded into Q pre-tf32

    // ---- stage Q (prescaled, tf32-rounded) ----
    #pragma unroll
    for (int i = tid; i < BM * DIM / 4; i += NTHREADS) {
        float4 x = ((const float4*)qg)[i];
        int r = i >> 4, c = (i & 15) << 2;
        float* d = Qs + r * QST + c;
        d[0] = f2tf32(x.x * scale); d[1] = f2tf32(x.y * scale);
        d[2] = f2tf32(x.z * scale); d[3] = f2tf32(x.w * scale);
    }

    const int mrow = wid * 16;

    float m0 = -INFINITY, m1 = -INFINITY, l0 = 0.f, l1 = 0.f;
    float acc[8][4];
    #pragma unroll
    for (int nt = 0; nt < 8; nt++)
        #pragma unroll
        for (int j = 0; j < 4; j++) acc[nt][j] = 0.f;

    for (int kt = 0; kt < SEQ / BN; kt++) {
        __syncthreads();  // prior PV reads of Vs done

        // ---- stage K, V (tf32-rounded) ----
        const float4* kgt = (const float4*)(kg + (size_t)kt * BN * DIM);
        const float4* vgt = (const float4*)(vg + (size_t)kt * BN * DIM);
        #pragma unroll
        for (int i = tid; i < BN * DIM / 4; i += NTHREADS) {
            int r = i >> 4, c = (i & 15) << 2;
            float4 x = kgt[i];
            float* dk = Ks + r * KST + c;
            dk[0] = f2tf32(x.x); dk[1] = f2tf32(x.y);
            dk[2] = f2tf32(x.z); dk[3] = f2tf32(x.w);
            float4 y = vgt[i];
            float* dv = Vs + r * VST + c;
            dv[0] = f2tf32(y.x); dv[1] = f2tf32(y.y);
            dv[2] = f2tf32(y.z); dv[3] = f2tf32(y.w);
        }
        __syncthreads();

        // ---- S = Q @ K^T : 8 k-chunks x 8 n-tiles of m16n8k8 ----
        float s[8][4];
        #pragma unroll
        for (int nt = 0; nt < 8; nt++)
            #pragma unroll
            for (int j = 0; j < 4; j++) s[nt][j] = 0.f;

        #pragma unroll
        for (int kc = 0; kc < 8; kc++) {
            uint32_t a[4];
            const float* qb = Qs + (mrow + g) * QST + kc * 8 + t;
            a[0] = __float_as_uint(qb[0]);
            a[1] = __float_as_uint(qb[8 * QST]);
            a[2] = __float_as_uint(qb[4]);
            a[3] = __float_as_uint(qb[8 * QST + 4]);
            #pragma unroll
            for (int nt = 0; nt < 8; nt++) {
                uint32_t bb[2];
                const float* kb = Ks + (nt * 8 + g) * KST + kc * 8 + t;
                bb[0] = __float_as_uint(kb[0]);
                bb[1] = __float_as_uint(kb[4]);
                mma_tf32(s[nt], a, bb);
            }
        }

        // ---- online softmax (rows g and g+8; reduce across the 4-lane quad) ----
        float rmax0 = -INFINITY, rmax1 = -INFINITY;
        #pragma unroll
        for (int nt = 0; nt < 8; nt++) {
            rmax0 = fmaxf(rmax0, fmaxf(s[nt][0], s[nt][1]));
            rmax1 = fmaxf(rmax1, fmaxf(s[nt][2], s[nt][3]));
        }
        #pragma unroll
        for (int off = 1; off <= 2; off <<= 1) {
            rmax0 = fmaxf(rmax0, __shfl_xor_sync(0xffffffffu, rmax0, off));
            rmax1 = fmaxf(rmax1, __shfl_xor_sync(0xffffffffu, rmax1, off));
        }
        float mn0 = fmaxf(m0, rmax0), mn1 = fmaxf(m1, rmax1);
        float corr0 = __expf(m0 - mn0), corr1 = __expf(m1 - mn1);
        float rs0 = 0.f, rs1 = 0.f;
        #pragma unroll
        for (int nt = 0; nt < 8; nt++) {
            s[nt][0] = __expf(s[nt][0] - mn0);
            s[nt][1] = __expf(s[nt][1] - mn0);
            s[nt][2] = __expf(s[nt][2] - mn1);
            s[nt][3] = __expf(s[nt][3] - mn1);
            rs0 += s[nt][0] + s[nt][1];
            rs1 += s[nt][2] + s[nt][3];
        }
        #pragma unroll
        for (int off = 1; off <= 2; off <<= 1) {
            rs0 += __shfl_xor_sync(0xffffffffu, rs0, off);
            rs1 += __shfl_xor_sync(0xffffffffu, rs1, off);
        }
        l0 = l0 * corr0 + rs0; m0 = mn0;
        l1 = l1 * corr1 + rs1; m1 = mn1;
        #pragma unroll
        for (int nt = 0; nt < 8; nt++) {
            acc[nt][0] *= corr0; acc[nt][1] *= corr0;
            acc[nt][2] *= corr1; acc[nt][3] *= corr1;
        }

        // ---- stage P (C-layout -> smem, tf32-rounded); warp-private rows ----
        #pragma unroll
        for (int nt = 0; nt < 8; nt++) {
            float* p0 = Ps + (mrow + g) * PST + nt * 8 + 2 * t;
            p0[0] = f2tf32(s[nt][0]); p0[1] = f2tf32(s[nt][1]);
            float* p1 = p0 + 8 * PST;
            p1[0] = f2tf32(s[nt][2]); p1[1] = f2tf32(s[nt][3]);
        }
        __syncwarp();

        // ---- O += P @ V : 8 j-chunks x 8 d-tiles ----
        #pragma unroll
        for (int kc = 0; kc < 8; kc++) {
            uint32_t a[4];
            const float* pb = Ps + (mrow + g) * PST + kc * 8 + t;
            a[0] = __float_as_uint(pb[0]);
            a[1] = __float_as_uint(pb[8 * PST]);
            a[2] = __float_as_uint(pb[4]);
            a[3] = __float_as_uint(pb[8 * PST + 4]);
            #pragma unroll
            for (int nt = 0; nt < 8; nt++) {
                uint32_t bb[2];
                const float* vb = Vs + (kc * 8 + t) * VST + nt * 8 + g;
                bb[0] = __float_as_uint(vb[0]);
                bb[1] = __float_as_uint(vb[4 * VST]);
                mma_tf32(acc[nt], a, bb);
            }
        }
    }

    // ---- epilogue: normalize, float2 stores ----
    float inv0 = 1.0f / l0, inv1 = 1.0f / l1;
    #pragma unroll
    for (int nt = 0; nt < 8; nt++) {
        float2 o0 = make_float2(acc[nt][0] * inv0, acc[nt][1] * inv0);
        float2 o1 = make_float2(acc[nt][2] * inv1, acc[nt][3] * inv1);
        *(float2*)(og + (size_t)(mrow + g) * DIM + nt * 8 + 2 * t) = o0;
        *(float2*)(og + (size_t)(mrow + g + 8) * DIM + nt * 8 + 2 * t) = o1;
    }
}

extern "C" void kernel_launch(void* const* d_in, const int* in_sizes, int n_in,
                              void* d_out, int out_size) {
    const float* q = (const float*)d_in[0];
    const float* k = (const float*)d_in[1];
    const float* v = (const float*)d_in[2];
    float* o = (float*)d_out;

    const int smem_bytes =
        (BM * QST + BN * KST + BN * VST + BM * PST) * (int)sizeof(float);  // 70656

    cudaFuncSetAttribute(attn_kernel,
                         cudaFuncAttributeMaxDynamicSharedMemorySize, smem_bytes);

    dim3 grid(SEQ / BM, HEADS, BATCH);  // (32, 16, 4)
    attn_kernel<<<grid, NTHREADS, smem_bytes>>>(q, k, v, o);
}

// round 4
// speedup vs baseline: 4.1973x; 1.3523x over previous
#include <cuda_runtime.h>
#include <math.h>
#include <stdint.h>

#define BATCH    4
#define HEADS    16
#define SEQ      2048
#define DIM      64
#define BM       128   // 4 warps x 32 rows
#define BN       64
#define NTHREADS 128

// smem strides in floats (conflict-free scalar fragment loads)
#define QST 68
#define KST 68
#define VST 72

__device__ __forceinline__ float f2tf32(float x) {
    uint32_t r;
    asm("cvt.rna.tf32.f32 %0, %1;" : "=r"(r) : "f"(x));
    return __uint_as_float(r);
}

__device__ __forceinline__ void mma_tf32(float c[4], const uint32_t a[4], const uint32_t b[2]) {
    asm volatile(
        "mma.sync.aligned.m16n8k8.row.col.f32.tf32.tf32.f32 "
        "{%0,%1,%2,%3}, {%4,%5,%6,%7}, {%8,%9}, {%0,%1,%2,%3};\n"
        : "+f"(c[0]), "+f"(c[1]), "+f"(c[2]), "+f"(c[3])
        : "r"(a[0]), "r"(a[1]), "r"(a[2]), "r"(a[3]), "r"(b[0]), "r"(b[1]));
}

// Flash-attention, tf32 mma, fp32 accumulate.
// Warp w owns 32 query rows [32w, 32w+32) as two m16 row-blocks rb=0,1.
// m16n8k8 per-thread fragments (g=lane>>2, t=lane&3):
//   A: a0=(g,t) a1=(g+8,t) a2=(g,t+4) a3=(g+8,t+4)
//   B: b0=(k=t,n=g) b1=(k=t+4,n=g)
//   C: c0=(g,2t) c1=(g,2t+1) c2=(g+8,2t) c3=(g+8,2t+1)
// P never touches smem: C-layout -> A-layout via quad shuffles.
__global__ __launch_bounds__(NTHREADS, 2)
void attn_kernel(const float* __restrict__ q, const float* __restrict__ k,
                 const float* __restrict__ v, float* __restrict__ out) {
    extern __shared__ float sm[];
    float* Qs = sm;                  // BM x QST
    float* Ks = Qs + BM * QST;       // BN x KST
    float* Vs = Ks + BN * KST;       // BN x VST

    const int tid  = threadIdx.x;
    const int wid  = tid >> 5;
    const int lane = tid & 31;
    const int g = lane >> 2;
    const int t = lane & 3;

    const int qblk = blockIdx.x;
    const int h    = blockIdx.y;
    const int b    = blockIdx.z;

    const float* qg = q + ((size_t)((b * HEADS + h) * SEQ + qblk * BM)) * DIM;
    const float* kg = k + (size_t)b * SEQ * DIM;
    const float* vg = v + (size_t)b * SEQ * DIM;
    float*       og = out + ((size_t)((b * HEADS + h) * SEQ + qblk * BM)) * DIM;

    const float scale = 0.125f;  // 1/sqrt(64), folded into Q pre-tf32

    // ---- stage Q (prescaled, tf32-rounded) ----
    #pragma unroll
    for (int i = tid; i < BM * DIM / 4; i += NTHREADS) {
        float4 x = ((const float4*)qg)[i];
        int r = i >> 4, c = (i & 15) << 2;
        float* d = Qs + r * QST + c;
        d[0] = f2tf32(x.x * scale); d[1] = f2tf32(x.y * scale);
        d[2] = f2tf32(x.z * scale); d[3] = f2tf32(x.w * scale);
    }

    const int mbase = wid * 32;
    // shuffle source lanes for the C->A remap
    const int src0 = (lane & ~3) | (t >> 1);
    const int src2 = src0 + 2;
    const bool odd = t & 1;

    float m[2][2], l[2][2], acc[2][8][4];
    #pragma unroll
    for (int rb = 0; rb < 2; rb++) {
        m[rb][0] = -INFINITY; m[rb][1] = -INFINITY;
        l[rb][0] = 0.f;       l[rb][1] = 0.f;
        #pragma unroll
        for (int nt = 0; nt < 8; nt++)
            #pragma unroll
            for (int j = 0; j < 4; j++) acc[rb][nt][j] = 0.f;
    }

    for (int kt = 0; kt < SEQ / BN; kt++) {
        __syncthreads();  // prior tile's PV reads of Vs done

        // ---- stage K, V (tf32-rounded) ----
        const float4* kgt = (const float4*)(kg + (size_t)kt * BN * DIM);
        const float4* vgt = (const float4*)(vg + (size_t)kt * BN * DIM);
        #pragma unroll
        for (int i = tid; i < BN * DIM / 4; i += NTHREADS) {
            int r = i >> 4, c = (i & 15) << 2;
            float4 x = kgt[i];
            float* dk = Ks + r * KST + c;
            dk[0] = f2tf32(x.x); dk[1] = f2tf32(x.y);
            dk[2] = f2tf32(x.z); dk[3] = f2tf32(x.w);
            float4 y = vgt[i];
            float* dv = Vs + r * VST + c;
            dv[0] = f2tf32(y.x); dv[1] = f2tf32(y.y);
            dv[2] = f2tf32(y.z); dv[3] = f2tf32(y.w);
        }
        __syncthreads();

        // ---- S = Q @ K^T : K-fragments shared across both row-blocks ----
        float s[2][8][4];
        #pragma unroll
        for (int rb = 0; rb < 2; rb++)
            #pragma unroll
            for (int nt = 0; nt < 8; nt++)
                #pragma unroll
                for (int j = 0; j < 4; j++) s[rb][nt][j] = 0.f;

        #pragma unroll
        for (int kc = 0; kc < 8; kc++) {
            uint32_t a[2][4];
            #pragma unroll
            for (int rb = 0; rb < 2; rb++) {
                const float* qb = Qs + (mbase + 16 * rb + g) * QST + kc * 8 + t;
                a[rb][0] = __float_as_uint(qb[0]);
                a[rb][1] = __float_as_uint(qb[8 * QST]);
                a[rb][2] = __float_as_uint(qb[4]);
                a[rb][3] = __float_as_uint(qb[8 * QST + 4]);
            }
            #pragma unroll
            for (int nt = 0; nt < 8; nt++) {
                uint32_t bb[2];
                const float* kb = Ks + (nt * 8 + g) * KST + kc * 8 + t;
                bb[0] = __float_as_uint(kb[0]);
                bb[1] = __float_as_uint(kb[4]);
                mma_tf32(s[0][nt], a[0], bb);
                mma_tf32(s[1][nt], a[1], bb);
            }
        }

        // ---- online softmax per row-block (quad reduction) ----
        #pragma unroll
        for (int rb = 0; rb < 2; rb++) {
            float rmax0 = -INFINITY, rmax1 = -INFINITY;
            #pragma unroll
            for (int nt = 0; nt < 8; nt++) {
                rmax0 = fmaxf(rmax0, fmaxf(s[rb][nt][0], s[rb][nt][1]));
                rmax1 = fmaxf(rmax1, fmaxf(s[rb][nt][2], s[rb][nt][3]));
            }
            #pragma unroll
            for (int off = 1; off <= 2; off <<= 1) {
                rmax0 = fmaxf(rmax0, __shfl_xor_sync(0xffffffffu, rmax0, off));
                rmax1 = fmaxf(rmax1, __shfl_xor_sync(0xffffffffu, rmax1, off));
            }
            float mn0 = fmaxf(m[rb][0], rmax0), mn1 = fmaxf(m[rb][1], rmax1);
            float corr0 = __expf(m[rb][0] - mn0), corr1 = __expf(m[rb][1] - mn1);
            float rs0 = 0.f, rs1 = 0.f;
            #pragma unroll
            for (int nt = 0; nt < 8; nt++) {
                s[rb][nt][0] = __expf(s[rb][nt][0] - mn0);
                s[rb][nt][1] = __expf(s[rb][nt][1] - mn0);
                s[rb][nt][2] = __expf(s[rb][nt][2] - mn1);
                s[rb][nt][3] = __expf(s[rb][nt][3] - mn1);
                rs0 += s[rb][nt][0] + s[rb][nt][1];
                rs1 += s[rb][nt][2] + s[rb][nt][3];
            }
            #pragma unroll
            for (int off = 1; off <= 2; off <<= 1) {
                rs0 += __shfl_xor_sync(0xffffffffu, rs0, off);
                rs1 += __shfl_xor_sync(0xffffffffu, rs1, off);
            }
            l[rb][0] = l[rb][0] * corr0 + rs0; m[rb][0] = mn0;
            l[rb][1] = l[rb][1] * corr1 + rs1; m[rb][1] = mn1;
            #pragma unroll
            for (int nt = 0; nt < 8; nt++) {
                acc[rb][nt][0] *= corr0; acc[rb][nt][1] *= corr0;
                acc[rb][nt][2] *= corr1; acc[rb][nt][3] *= corr1;
            }
        }

        // ---- O += P @ V : P from registers via quad-shuffle remap ----
        #pragma unroll
        for (int kc = 0; kc < 8; kc++) {
            uint32_t a[2][4];
            #pragma unroll
            for (int rb = 0; rb < 2; rb++) {
                float e0 = __shfl_sync(0xffffffffu, s[rb][kc][0], src0);
                float e1 = __shfl_sync(0xffffffffu, s[rb][kc][1], src0);
                float e2 = __shfl_sync(0xffffffffu, s[rb][kc][2], src0);
                float e3 = __shfl_sync(0xffffffffu, s[rb][kc][3], src0);
                float f0 = __shfl_sync(0xffffffffu, s[rb][kc][0], src2);
                float f1 = __shfl_sync(0xffffffffu, s[rb][kc][1], src2);
                float f2 = __shfl_sync(0xffffffffu, s[rb][kc][2], src2);
                float f3 = __shfl_sync(0xffffffffu, s[rb][kc][3], src2);
                a[rb][0] = __float_as_uint(f2tf32(odd ? e1 : e0));
                a[rb][1] = __float_as_uint(f2tf32(odd ? e3 : e2));
                a[rb][2] = __float_as_uint(f2tf32(odd ? f1 : f0));
                a[rb][3] = __float_as_uint(f2tf32(odd ? f3 : f2));
            }
            #pragma unroll
            for (int nt = 0; nt < 8; nt++) {
                uint32_t bb[2];
                const float* vb = Vs + (kc * 8 + t) * VST + nt * 8 + g;
                bb[0] = __float_as_uint(vb[0]);
                bb[1] = __float_as_uint(vb[4 * VST]);
                mma_tf32(acc[0][nt], a[0], bb);
                mma_tf32(acc[1][nt], a[1], bb);
            }
        }
    }

    // ---- epilogue: normalize, float2 stores ----
    #pragma unroll
    for (int rb = 0; rb < 2; rb++) {
        float inv0 = 1.0f / l[rb][0], inv1 = 1.0f / l[rb][1];
        const int r = mbase + 16 * rb + g;
        #pragma unroll
        for (int nt = 0; nt < 8; nt++) {
            float2 o0 = make_float2(acc[rb][nt][0] * inv0, acc[rb][nt][1] * inv0);
            float2 o1 = make_float2(acc[rb][nt][2] * inv1, acc[rb][nt][3] * inv1);
            *(float2*)(og + (size_t)r * DIM + nt * 8 + 2 * t) = o0;
            *(float2*)(og + (size_t)(r + 8) * DIM + nt * 8 + 2 * t) = o1;
        }
    }
}

extern "C" void kernel_launch(void* const* d_in, const int* in_sizes, int n_in,
                              void* d_out, int out_size) {
    const float* q = (const float*)d_in[0];
    const float* k = (const float*)d_in[1];
    const float* v = (const float*)d_in[2];
    float* o = (float*)d_out;

    const int smem_bytes =
        (BM * QST + BN * KST + BN * VST) * (int)sizeof(float);  // 70656

    cudaFuncSetAttribute(attn_kernel,
                         cudaFuncAttributeMaxDynamicSharedMemorySize, smem_bytes);

    dim3 grid(SEQ / BM, HEADS, BATCH);  // (16, 16, 4) = 1024 blocks
    attn_kernel<<<grid, NTHREADS, smem_bytes>>>(q, k, v, o);
}